// round 2
// baseline (speedup 1.0000x reference)
#include <cuda_runtime.h>
#include <cstdint>
#include <cstddef>

#define B_ 8
#define N_ 2048
#define F_ 512
#define D_ 512

// Scratch (static device globals — allocation-free rule)
__device__ float g_t[(size_t)B_ * N_ * F_];   // intermediate t = a @ x
__device__ float g_mask[B_ * N_];             // per-row mask from x

__device__ __forceinline__ uint32_t f2tf(float f) {
    uint32_t r;
    asm("cvt.rna.tf32.f32 %0, %1;" : "=r"(r) : "f"(f));
    return r;
}

// ---------------------------------------------------------------------------
// mask[row] = any(x[row, :] != 0)
// ---------------------------------------------------------------------------
__global__ void mask_kernel(const float* __restrict__ x, float* __restrict__ mask) {
    int row = blockIdx.x;  // 0 .. B_*N_-1
    const float4* xr = (const float4*)(x + (size_t)row * F_);
    int nz = 0;
    for (int i = threadIdx.x; i < F_ / 4; i += blockDim.x) {
        float4 v = xr[i];
        nz |= (v.x != 0.f) | (v.y != 0.f) | (v.z != 0.f) | (v.w != 0.f);
    }
    nz = __syncthreads_or(nz);
    if (threadIdx.x == 0) mask[row] = nz ? 1.0f : 0.0f;
}

// ---------------------------------------------------------------------------
// Generic tf32 GEMM: C[M,Nd] = A[M,K] @ B[K,Nd], row-major, fp32 accumulate.
// CTA tile 128x128x32, 256 threads, 4x2 warps, warp tile 32x64 (m16n8k8 mma).
// EPI: fused relu + row-mask epilogue (GEMM2).
// ---------------------------------------------------------------------------
constexpr int BM = 128, BN = 128, BK = 32;
constexpr int APAD = 36;   // A smem row stride (elems): (36*r + c) % 32 = 4r+c -> conflict-free
constexpr int BPAD = 136;  // B smem row stride: (136*k + n) % 32 = 8k+n -> conflict-free
constexpr size_t SMEM_BYTES = (size_t)(2 * BM * APAD + 2 * BK * BPAD) * 4;

template <bool EPI>
__global__ __launch_bounds__(256, 1)
void gemm_tf32(const float* __restrict__ A, const float* __restrict__ Bm,
               float* __restrict__ C, int K, int lda, int ldb, int ldc,
               size_t sA, size_t sB, size_t sC,
               const float* __restrict__ mask) {
    extern __shared__ uint32_t smem[];
    uint32_t* As = smem;                      // [2][BM*APAD]
    uint32_t* Bs = smem + 2 * BM * APAD;      // [2][BK*BPAD]

    const int tid = threadIdx.x;
    const int ln  = tid & 31;
    const int warp = tid >> 5;
    const int wm = warp >> 1;   // 0..3
    const int wn = warp & 1;    // 0..1
    const int row0 = blockIdx.y * BM;
    const int col0 = blockIdx.x * BN;

    const float* Ab = A + (size_t)blockIdx.z * sA + (size_t)row0 * lda;
    const float* Bb = Bm + (size_t)blockIdx.z * sB;
    float*       Cb = C + (size_t)blockIdx.z * sC;

    float4 ra[4], rb[4];

    auto ldg = [&](int k0) {
#pragma unroll
        for (int i = 0; i < 4; i++) {
            int idx = tid + i * 256;           // 0..1023
            int r = idx >> 3, c4 = idx & 7;    // A: 128 rows x 8 float4
            ra[i] = *(const float4*)(Ab + (size_t)r * lda + k0 + c4 * 4);
        }
#pragma unroll
        for (int i = 0; i < 4; i++) {
            int idx = tid + i * 256;
            int r = idx >> 5, c4 = idx & 31;   // B: 32 rows x 32 float4
            rb[i] = *(const float4*)(Bb + (size_t)(k0 + r) * ldb + col0 + c4 * 4);
        }
    };
    auto sts = [&](int s) {
        uint32_t* as = As + s * BM * APAD;
        uint32_t* bs = Bs + s * BK * BPAD;
#pragma unroll
        for (int i = 0; i < 4; i++) {
            int idx = tid + i * 256;
            int r = idx >> 3, c4 = idx & 7;
            uint4 v = make_uint4(f2tf(ra[i].x), f2tf(ra[i].y), f2tf(ra[i].z), f2tf(ra[i].w));
            *(uint4*)(as + r * APAD + c4 * 4) = v;
        }
#pragma unroll
        for (int i = 0; i < 4; i++) {
            int idx = tid + i * 256;
            int r = idx >> 5, c4 = idx & 31;
            uint4 v = make_uint4(f2tf(rb[i].x), f2tf(rb[i].y), f2tf(rb[i].z), f2tf(rb[i].w));
            *(uint4*)(bs + r * BPAD + c4 * 4) = v;
        }
    };

    float acc[2][8][4] = {};
    uint32_t af[2][4], bf[8][2];

    ldg(0);
    sts(0);
    __syncthreads();

    const int nk = K / BK;
    for (int k0 = 0; k0 < nk; ++k0) {
        const int cur = k0 & 1;
        if (k0 + 1 < nk) ldg((k0 + 1) * BK);

        const uint32_t* as = As + cur * BM * APAD;
        const uint32_t* bs = Bs + cur * BK * BPAD;
#pragma unroll
        for (int kk = 0; kk < 4; kk++) {
            const int kb = kk * 8;
#pragma unroll
            for (int im = 0; im < 2; im++) {
                int r = wm * 32 + im * 16 + (ln >> 2);
                int c = kb + (ln & 3);
                af[im][0] = as[r * APAD + c];
                af[im][1] = as[(r + 8) * APAD + c];
                af[im][2] = as[r * APAD + c + 4];
                af[im][3] = as[(r + 8) * APAD + c + 4];
            }
#pragma unroll
            for (int in = 0; in < 8; in++) {
                int cn = wn * 64 + in * 8 + (ln >> 2);
                bf[in][0] = bs[(kb + (ln & 3)) * BPAD + cn];
                bf[in][1] = bs[(kb + (ln & 3) + 4) * BPAD + cn];
            }
#pragma unroll
            for (int im = 0; im < 2; im++)
#pragma unroll
                for (int in = 0; in < 8; in++) {
                    asm volatile(
                        "mma.sync.aligned.m16n8k8.row.col.f32.tf32.tf32.f32 "
                        "{%0,%1,%2,%3}, {%4,%5,%6,%7}, {%8,%9}, {%0,%1,%2,%3};"
                        : "+f"(acc[im][in][0]), "+f"(acc[im][in][1]),
                          "+f"(acc[im][in][2]), "+f"(acc[im][in][3])
                        : "r"(af[im][0]), "r"(af[im][1]), "r"(af[im][2]), "r"(af[im][3]),
                          "r"(bf[in][0]), "r"(bf[in][1]));
                }
        }
        __syncthreads();
        if (k0 + 1 < nk) {
            sts(cur ^ 1);
            __syncthreads();
        }
    }

    // Epilogue
#pragma unroll
    for (int im = 0; im < 2; im++) {
        int rbase = row0 + wm * 32 + im * 16 + (ln >> 2);
#pragma unroll
        for (int half = 0; half < 2; half++) {
            int r = rbase + half * 8;
            float mk = 1.0f;
            if (EPI) mk = mask[r];  // rows are global for GEMM2
            float* crow = Cb + (size_t)r * ldc;
#pragma unroll
            for (int in = 0; in < 8; in++) {
                int cc = col0 + wn * 64 + in * 8 + 2 * (ln & 3);
                float v0 = acc[im][in][half * 2 + 0];
                float v1 = acc[im][in][half * 2 + 1];
                if (EPI) {
                    v0 = fmaxf(v0, 0.f) * mk;
                    v1 = fmaxf(v1, 0.f) * mk;
                }
                *(float2*)(crow + cc) = make_float2(v0, v1);
            }
        }
    }
}

// ---------------------------------------------------------------------------
extern "C" void kernel_launch(void* const* d_in, const int* in_sizes, int n_in,
                              void* d_out, int out_size) {
    const float *x = nullptr, *a = nullptr, *w = nullptr;
    for (int i = 0; i < n_in; i++) {
        if (in_sizes[i] == B_ * N_ * N_)      a = (const float*)d_in[i];
        else if (in_sizes[i] == F_ * D_)      w = (const float*)d_in[i];
        else                                  x = (const float*)d_in[i];
    }
    float* out = (float*)d_out;

    float *t_ptr, *mask_ptr;
    cudaGetSymbolAddress((void**)&t_ptr, g_t);
    cudaGetSymbolAddress((void**)&mask_ptr, g_mask);

    cudaFuncSetAttribute(gemm_tf32<false>, cudaFuncAttributeMaxDynamicSharedMemorySize, SMEM_BYTES);
    cudaFuncSetAttribute(gemm_tf32<true>,  cudaFuncAttributeMaxDynamicSharedMemorySize, SMEM_BYTES);

    // mask from x
    mask_kernel<<<B_ * N_, 128>>>(x, mask_ptr);

    // GEMM1: t[b] = a[b] (2048x2048) @ x[b] (2048x512)
    gemm_tf32<false><<<dim3(F_ / BN, N_ / BM, B_), 256, SMEM_BYTES>>>(
        a, x, t_ptr, /*K=*/N_, /*lda=*/N_, /*ldb=*/F_, /*ldc=*/F_,
        (size_t)N_ * N_, (size_t)N_ * F_, (size_t)N_ * F_, nullptr);

    // GEMM2: out = relu(t (16384x512) @ W (512x512)) * mask
    gemm_tf32<true><<<dim3(D_ / BN, (B_ * N_) / BM, 1), 256, SMEM_BYTES>>>(
        t_ptr, w, out, /*K=*/F_, /*lda=*/F_, /*ldb=*/D_, /*ldc=*/D_,
        0, 0, 0, mask_ptr);
}